// round 9
// baseline (speedup 1.0000x reference)
#include <cuda_runtime.h>

#define LSEQ    2048
#define NBATCH  32
#define NROWS   (NBATCH * LSEQ)     // 65536
#define TPB     128
#define NBLOCKS 444                 // 3 per SM (148 SMs), no smem
#define NWARPS  (NBLOCKS * 4)       // 1776
#define NCHUNKS 64                  // 32-query chunks per batch
#define NUNITS  (NBATCH * NCHUNKS)  // 2048
#define DTC     0.01f

// log2(e)/sqrt(3): folds softmax scale + e^x->2^x into q
#define QSCALE  (1.4426950408889634f / 1.7320508075688772f)

// Scratch (device globals: allocation-free). 3 MB total -> L2-resident.
__device__ float4   g_Q[NROWS];         // {q0,q1,q2,0}, pre-scaled by QSCALE
__device__ float4   g_KV[NROWS * 2];    // [b*4096 + 2j]={k0,k1,k2,0}, +1={v0,v1,v2,1}
__device__ unsigned g_ctr;

__global__ void reset_counter_kernel() { g_ctr = NWARPS; }

__device__ __forceinline__ float ex2(float x) {
    float r;
    asm("ex2.approx.f32 %0, %1;" : "=f"(r) : "f"(x));
    return r;
}

#define PACK2(d, lo, hi)   asm("mov.b64 %0, {%1, %2};" : "=l"(d) : "f"(lo), "f"(hi))
#define UNPACK2(lo, hi, d) asm("mov.b64 {%0, %1}, %2;" : "=f"(lo), "=f"(hi) : "l"(d))
#define FMA2(d, a, b, c)   asm("fma.rn.f32x2 %0, %1, %2, %3;" : "=l"(d) : "l"(a), "l"(b), "l"(c))

// ---------------- Pass 1: QKV projection into global scratch ----------------
__global__ void __launch_bounds__(TPB) qkv_kernel(
    const float* __restrict__ inputs,
    const float* __restrict__ wi, const float* __restrict__ bi,
    const float* __restrict__ sigma)
{
    int r = blockIdx.x * TPB + threadIdx.x;
    if (r >= NROWS) return;
    float inv0 = 1.0f / (sigma[0] + 1e-5f);
    float inv1 = 1.0f / (sigma[1] + 1e-5f);
    float x0 = inputs[3 * r + 0];
    float x1 = inputs[3 * r + 1] * inv0;
    float x2 = inputs[3 * r + 2] * inv1;

    float q0 = (bi[0] + wi[0] * x0 + wi[1] * x1 + wi[2] * x2) * QSCALE;
    float q1 = (bi[1] + wi[3] * x0 + wi[4] * x1 + wi[5] * x2) * QSCALE;
    float q2 = (bi[2] + wi[6] * x0 + wi[7] * x1 + wi[8] * x2) * QSCALE;
    float k0 =  bi[3] + wi[ 9] * x0 + wi[10] * x1 + wi[11] * x2;
    float k1 =  bi[4] + wi[12] * x0 + wi[13] * x1 + wi[14] * x2;
    float k2 =  bi[5] + wi[15] * x0 + wi[16] * x1 + wi[17] * x2;
    float v0 =  bi[6] + wi[18] * x0 + wi[19] * x1 + wi[20] * x2;
    float v1 =  bi[7] + wi[21] * x0 + wi[22] * x1 + wi[23] * x2;
    float v2 =  bi[8] + wi[24] * x0 + wi[25] * x1 + wi[26] * x2;

    g_Q[r]          = make_float4(q0, q1, q2, 0.0f);
    g_KV[2 * r + 0] = make_float4(k0, k1, k2, 0.0f);
    g_KV[2 * r + 1] = make_float4(v0, v1, v2, 1.0f);
}

// ---------------- Pass 2: attention + epilogue, warp-level scheduling --------
// Unit u (cost-descending): k = 63 - (u>>5), batch = u & 31.
// Warp gw seeds unit gw (all expensive units start at t=0); 272 cheap units stolen.
__global__ void __launch_bounds__(TPB) attn_kernel(
    const float* __restrict__ wo,  const float* __restrict__ bo,
    const float* __restrict__ f1w, const float* __restrict__ f1b,
    const float* __restrict__ f2w, const float* __restrict__ f2b,
    const float* __restrict__ g1w, const float* __restrict__ g1b,
    const float* __restrict__ g2w, const float* __restrict__ g2b,
    const float* __restrict__ m1s, const float* __restrict__ m2s,
    const float* __restrict__ sigma,
    float* __restrict__ out)
{
    const int lane = threadIdx.x & 31;
    const unsigned full = 0xffffffffu;
    unsigned unit = blockIdx.x * 4 + (threadIdx.x >> 5);   // seed: gw < NWARPS <= NUNITS

    const float scl0 = sigma[0] + 1e-5f;
    const float scl1 = sigma[1] + 1e-5f;

    while (unit < NUNITS) {
        const int k = 63 - (int)(unit >> 5);
        const int b = (int)(unit & 31u);
        const int i = (k << 5) + lane;                 // this lane's query index
        const float4* __restrict__ kv = g_KV + b * (2 * LSEQ);

        float4 Q = g_Q[b * LSEQ + i];
        const float q0 = Q.x, q1 = Q.y, q2 = Q.z;

        unsigned long long acc01 = 0ull, acc2d = 0ull;  // {a0,a1}, {a2,den}
        const int jmax = k << 5;

        #pragma unroll 4
        for (int j = 0; j < jmax; j++) {               // shared j-stream: broadcast LDG
            float4 K = kv[2 * j];
            float4 V = kv[2 * j + 1];
            float sc = fmaf(K.z, q2, fmaf(K.y, q1, K.x * q0));
            float w  = ex2(sc);
            unsigned long long wp, vp01, vp2d;
            PACK2(wp, w, w);
            PACK2(vp01, V.x, V.y);
            PACK2(vp2d, V.z, V.w);
            FMA2(acc01, wp, vp01, acc01);
            FMA2(acc2d, wp, vp2d, acc2d);
        }
        #pragma unroll 4
        for (int jt = 0; jt < 32; jt++) {              // causal tail, predicated
            float4 K = kv[2 * (jmax + jt)];
            float4 V = kv[2 * (jmax + jt) + 1];
            float sc = fmaf(K.z, q2, fmaf(K.y, q1, K.x * q0));
            float w  = (jt <= lane) ? ex2(sc) : 0.0f;
            unsigned long long wp, vp01, vp2d;
            PACK2(wp, w, w);
            PACK2(vp01, V.x, V.y);
            PACK2(vp2d, V.z, V.w);
            FMA2(acc01, wp, vp01, acc01);
            FMA2(acc2d, wp, vp2d, acc2d);
        }

        float a0, a1, a2, den;
        UNPACK2(a0, a1, acc01);
        UNPACK2(a2, den, acc2d);
        const float r  = 1.0f / den;
        const float x0 = a0 * r, x1 = a1 * r, x2 = a2 * r;

        // epilogue (params L1-hot)
        float wo10 = wo[3], wo11 = wo[4], wo12 = wo[5];
        float wo20 = wo[6], wo21 = wo[7], wo22 = wo[8];
        float bo1 = bo[1], bo2 = bo[2];
        float G10 = g1w[0], G11 = g1w[1], G12 = g1w[2], G1B = g1b[0];
        float G20 = g2w[0], G21 = g2w[1], G22 = g2w[2], G2B = g2b[0];
        float F10 = f1w[0], F11 = f1w[1], F12 = f1w[2], F1B = f1b[0];
        float F20 = f2w[0], F21 = f2w[1], F22 = f2w[2], F2B = f2b[0];
        float M1 = m1s[0], M2 = m2s[0];

        float s1 = bo1 + wo10 * x0 + wo11 * x1 + wo12 * x2;
        float s2 = bo2 + wo20 * x0 + wo21 * x1 + wo22 * x2;

        float o[8];
        {
            float d1 = (G10 + G11 * s1 + G12 * s2 + G1B) * M1;
            float d2 = (G20 + G21 * s1 + G22 * s2 + G2B) * M2;
            s1 += DTC * d1; s2 += DTC * d2;
            o[0] = s1 * scl0; o[1] = s2 * scl1;
        }
        {
            float d1 = (G10 + G11 * s1 + G12 * s2 + G1B) * M1;
            float d2 = (G20 + G21 * s1 + G22 * s2 + G2B) * M2;
            s1 += DTC * d1; s2 += DTC * d2;
            o[2] = s1 * scl0; o[3] = s2 * scl1;
        }
        {
            float d1 = (G10 + G11 * s1 + G12 * s2 + G1B) * M1;
            float d2 = (G20 + G21 * s1 + G22 * s2 + G2B) * M2;
            s1 += DTC * d1; s2 += DTC * d2;
            o[4] = s1 * scl0; o[5] = s2 * scl1;
        }
        {
            float v1 = (F10 + F11 * s1 + F12 * s2 + F1B) * M1;
            float v2 = (F20 + F21 * s1 + F22 * s2 + F2B) * M2;
            o[6] = (s1 + v1 * DTC) * scl0;
            o[7] = (s2 + v2 * DTC) * scl1;
        }

        float4* op = reinterpret_cast<float4*>(out) + ((size_t)(b * LSEQ + i)) * 2;
        op[0] = make_float4(o[0], o[1], o[2], o[3]);
        op[1] = make_float4(o[4], o[5], o[6], o[7]);

        // steal next unit (lane 0): plain-load exhaustion pre-check avoids
        // the end-of-kernel atomic pileup; atomicAdd only when work remains.
        unsigned nxt = NUNITS;
        if (lane == 0) {
            unsigned cur;
            asm volatile("ld.global.cg.u32 %0, [%1];" : "=r"(cur) : "l"(&g_ctr));
            if (cur < NUNITS) nxt = atomicAdd(&g_ctr, 1u);
        }
        unit = __shfl_sync(full, nxt, 0);
    }
}

extern "C" void kernel_launch(void* const* d_in, const int* in_sizes, int n_in,
                              void* d_out, int out_size)
{
    const float* inputs = (const float*)d_in[1];
    const float* wi     = (const float*)d_in[2];
    const float* bi     = (const float*)d_in[3];
    const float* wo     = (const float*)d_in[4];
    const float* bo     = (const float*)d_in[5];
    const float* f1w    = (const float*)d_in[6];
    const float* f1b    = (const float*)d_in[7];
    const float* f2w    = (const float*)d_in[8];
    const float* f2b    = (const float*)d_in[9];
    const float* g1w    = (const float*)d_in[10];
    const float* g1b    = (const float*)d_in[11];
    const float* g2w    = (const float*)d_in[12];
    const float* g2b    = (const float*)d_in[13];
    const float* m1s    = (const float*)d_in[14];
    const float* m2s    = (const float*)d_in[15];
    const float* sigma  = (const float*)d_in[16];
    float* out = (float*)d_out;

    reset_counter_kernel<<<1, 1>>>();
    qkv_kernel<<<(NROWS + TPB - 1) / TPB, TPB>>>(inputs, wi, bi, sigma);
    attn_kernel<<<NBLOCKS, TPB>>>(wo, bo, f1w, f1b, f2w, f2b,
                                  g1w, g1b, g2w, g2b, m1s, m2s, sigma, out);
}

// round 10
// speedup vs baseline: 4.9231x; 4.9231x over previous
#include <cuda_runtime.h>

#define LSEQ   2048
#define NBATCH 32
#define TPB    256
#define GSPLIT 8          // GSPLIT * 128 low-queries per batch
#define DTC    0.01f

// log2(e)/sqrt(3): fold softmax scale + e^x->2^x conversion into q
#define QSCALE (1.4426950408889634f / 1.7320508075688772f)

__device__ __forceinline__ float ex2(float x) {
    float r;
    asm("ex2.approx.f32 %0, %1;" : "=f"(r) : "f"(x));
    return r;
}

__global__ void __launch_bounds__(TPB) ac_kernel(
    const float* __restrict__ inputs,
    const float* __restrict__ wi,  const float* __restrict__ bi,
    const float* __restrict__ wo,  const float* __restrict__ bo,
    const float* __restrict__ f1w, const float* __restrict__ f1b,
    const float* __restrict__ f2w, const float* __restrict__ f2b,
    const float* __restrict__ g1w, const float* __restrict__ g1b,
    const float* __restrict__ g2w, const float* __restrict__ g2b,
    const float* __restrict__ m1s, const float* __restrict__ m2s,
    const float* __restrict__ sigma,
    float* __restrict__ out)
{
    extern __shared__ float smem_raw[];
    float4* sk4 = reinterpret_cast<float4*>(smem_raw);            // [LSEQ]: {k0,k1,k2,v0}
    float2* sv2 = reinterpret_cast<float2*>(smem_raw + 4 * LSEQ); // [LSEQ]: {v1,v2}

    const int g = blockIdx.x;
    const int b = blockIdx.y;
    const int t = threadIdx.x;

    const float scl0 = sigma[0] + 1e-5f;
    const float scl1 = sigma[1] + 1e-5f;
    const float inv0 = 1.0f / scl0;
    const float inv1 = 1.0f / scl1;
    const float* __restrict__ xb = inputs + (size_t)b * LSEQ * 3;

    // ---------------- Phase A: build packed K,V tile (48 KB) ----------------
    {
        float wk[9], wv[9], bk[3], bv[3];
        #pragma unroll
        for (int i = 0; i < 9; i++) { wk[i] = wi[9 + i]; wv[i] = wi[18 + i]; }
        #pragma unroll
        for (int i = 0; i < 3; i++) { bk[i] = bi[3 + i]; bv[i] = bi[6 + i]; }

        for (int r = t; r < LSEQ; r += TPB) {
            float x0 = xb[3 * r + 0];
            float x1 = xb[3 * r + 1] * inv0;
            float x2 = xb[3 * r + 2] * inv1;
            float k0 = bk[0] + wk[0] * x0 + wk[1] * x1 + wk[2] * x2;
            float k1 = bk[1] + wk[3] * x0 + wk[4] * x1 + wk[5] * x2;
            float k2 = bk[2] + wk[6] * x0 + wk[7] * x1 + wk[8] * x2;
            float v0 = bv[0] + wv[0] * x0 + wv[1] * x1 + wv[2] * x2;
            float v1 = bv[1] + wv[3] * x0 + wv[4] * x1 + wv[5] * x2;
            float v2 = bv[2] + wv[6] * x0 + wv[7] * x1 + wv[8] * x2;
            sk4[r] = make_float4(k0, k1, k2, v0);
            sv2[r] = make_float2(v1, v2);
        }
    }
    __syncthreads();

    // ------------- Phase B: one query per thread, mirrored halves -------------
    // threads 0..127: query i = g*128 + t          (short loops)
    // threads 128..255: query i = 2047 - (g*128+u) (long loops)
    // Block total work identical to R1's pair scheme; warps of different cost
    // coexist and the SMSP arbiter fills gaps (4 warps/SMSP on loaded SMs).
    const int u = t & 127;
    const int p = g * 128 + u;
    const int i = (t < 128) ? p : (LSEQ - 1 - p);

    // q projection (gmem, L1-hot), pre-scaled for ex2
    float q0, q1, q2;
    {
        float x0 = xb[3 * i + 0];
        float x1 = xb[3 * i + 1] * inv0;
        float x2 = xb[3 * i + 2] * inv1;
        q0 = (bi[0] + wi[0] * x0 + wi[1] * x1 + wi[2] * x2) * QSCALE;
        q1 = (bi[1] + wi[3] * x0 + wi[4] * x1 + wi[5] * x2) * QSCALE;
        q2 = (bi[2] + wi[6] * x0 + wi[7] * x1 + wi[8] * x2) * QSCALE;
    }

    float den = 0.0f, a0 = 0.0f, a1 = 0.0f, a2 = 0.0f;
    #pragma unroll 4
    for (int j = 0; j <= i; j++) {
        float4 kf = sk4[j];          // broadcast LDS.128
        float s = q0 * kf.x + q1 * kf.y + q2 * kf.z;
        float w = ex2(s);
        float2 vf = sv2[j];          // broadcast LDS.64
        den += w;
        a0 += w * kf.w;
        a1 += w * vf.x;
        a2 += w * vf.y;
    }
    const float r  = 1.0f / den;
    const float c0 = a0 * r, c1 = a1 * r, c2 = a2 * r;

    // -------- epilogue (params L1-hot) --------
    float wo10 = wo[3], wo11 = wo[4], wo12 = wo[5];
    float wo20 = wo[6], wo21 = wo[7], wo22 = wo[8];
    float bo1 = bo[1], bo2 = bo[2];
    float G10 = g1w[0], G11 = g1w[1], G12 = g1w[2], G1B = g1b[0];
    float G20 = g2w[0], G21 = g2w[1], G22 = g2w[2], G2B = g2b[0];
    float F10 = f1w[0], F11 = f1w[1], F12 = f1w[2], F1B = f1b[0];
    float F20 = f2w[0], F21 = f2w[1], F22 = f2w[2], F2B = f2b[0];
    float M1 = m1s[0], M2 = m2s[0];

    float s1 = bo1 + wo10 * c0 + wo11 * c1 + wo12 * c2;
    float s2 = bo2 + wo20 * c0 + wo21 * c1 + wo22 * c2;

    float o[8];
    {
        float d1 = (G10 + G11 * s1 + G12 * s2 + G1B) * M1;
        float d2 = (G20 + G21 * s1 + G22 * s2 + G2B) * M2;
        s1 += DTC * d1; s2 += DTC * d2;
        o[0] = s1 * scl0; o[1] = s2 * scl1;
    }
    {
        float d1 = (G10 + G11 * s1 + G12 * s2 + G1B) * M1;
        float d2 = (G20 + G21 * s1 + G22 * s2 + G2B) * M2;
        s1 += DTC * d1; s2 += DTC * d2;
        o[2] = s1 * scl0; o[3] = s2 * scl1;
    }
    {
        float d1 = (G10 + G11 * s1 + G12 * s2 + G1B) * M1;
        float d2 = (G20 + G21 * s1 + G22 * s2 + G2B) * M2;
        s1 += DTC * d1; s2 += DTC * d2;
        o[4] = s1 * scl0; o[5] = s2 * scl1;
    }
    {
        float v1 = (F10 + F11 * s1 + F12 * s2 + F1B) * M1;
        float v2 = (F20 + F21 * s1 + F22 * s2 + F2B) * M2;
        o[6] = (s1 + v1 * DTC) * scl0;
        o[7] = (s2 + v2 * DTC) * scl1;
    }

    float4* op = reinterpret_cast<float4*>(out) + ((size_t)(b * LSEQ + i)) * 2;
    op[0] = make_float4(o[0], o[1], o[2], o[3]);
    op[1] = make_float4(o[4], o[5], o[6], o[7]);
}

extern "C" void kernel_launch(void* const* d_in, const int* in_sizes, int n_in,
                              void* d_out, int out_size)
{
    const float* inputs = (const float*)d_in[1];
    const float* wi     = (const float*)d_in[2];
    const float* bi     = (const float*)d_in[3];
    const float* wo     = (const float*)d_in[4];
    const float* bo     = (const float*)d_in[5];
    const float* f1w    = (const float*)d_in[6];
    const float* f1b    = (const float*)d_in[7];
    const float* f2w    = (const float*)d_in[8];
    const float* f2b    = (const float*)d_in[9];
    const float* g1w    = (const float*)d_in[10];
    const float* g1b    = (const float*)d_in[11];
    const float* g2w    = (const float*)d_in[12];
    const float* g2b    = (const float*)d_in[13];
    const float* m1s    = (const float*)d_in[14];
    const float* m2s    = (const float*)d_in[15];
    const float* sigma  = (const float*)d_in[16];
    float* out = (float*)d_out;

    const int smem = LSEQ * (16 + 8);   // 48 KB packed tile
    cudaFuncSetAttribute(ac_kernel, cudaFuncAttributeMaxDynamicSharedMemorySize, smem);

    dim3 grid(GSPLIT, NBATCH);          // 256 blocks x 256 threads
    ac_kernel<<<grid, TPB, smem>>>(inputs, wi, bi, wo, bo,
                                   f1w, f1b, f2w, f2b,
                                   g1w, g1b, g2w, g2b,
                                   m1s, m2s, sigma, out);
}